// round 1
// baseline (speedup 1.0000x reference)
#include <cuda_runtime.h>
#include <cuda_bf16.h>
#include <math.h>

// Problem constants
#define DIM     2048
#define NHEADS  16
#define HDIM    128
#define BATCH   2
#define SEQ     2048
#define MROWS   (BATCH*SEQ)     // 4096
#define WINHALF 128             // allowed: j - i <= 128

// ---------------- scratch (device globals: no allocation allowed) -------------
__device__ float g_q [MROWS*DIM];
__device__ float g_k [MROWS*DIM];
__device__ float g_v [MROWS*DIM];
__device__ float g_ao[MROWS*DIM];

// =====================================================================
// SGEMM:  C[M,N] = A[M,K] * B[N,K]^T   (both row-major, "NT" layout)
// 128x128 tile, BK=16, 256 threads, 8x8 microtile per thread.
// =====================================================================
__global__ __launch_bounds__(256, 2)
void sgemm_nt(const float* __restrict__ A, const float* __restrict__ B,
              float* __restrict__ C, int M, int N, int K)
{
    __shared__ float As[16][128];
    __shared__ float Bs[16][128];

    const int tid = threadIdx.x;
    const int tx  = tid & 15;
    const int ty  = tid >> 4;
    const int bm  = blockIdx.y * 128;
    const int bn  = blockIdx.x * 128;

    // loader mapping: 512 float4 per operand tile; thread handles f=tid (rows 0..63)
    // and f=tid+256 (rows 64..127)
    const int lrow = tid >> 2;            // 0..63
    const int lk4  = (tid & 3) * 4;       // 0,4,8,12

    const float* Aptr = A + (size_t)bm * K;
    const float* Bptr = B + (size_t)bn * K;

    float acc[8][8];
#pragma unroll
    for (int i = 0; i < 8; i++)
#pragma unroll
        for (int j = 0; j < 8; j++) acc[i][j] = 0.f;

    for (int k0 = 0; k0 < K; k0 += 16) {
        float4 a0 = *(const float4*)(Aptr + (size_t) lrow       * K + k0 + lk4);
        float4 a1 = *(const float4*)(Aptr + (size_t)(lrow + 64) * K + k0 + lk4);
        float4 b0 = *(const float4*)(Bptr + (size_t) lrow       * K + k0 + lk4);
        float4 b1 = *(const float4*)(Bptr + (size_t)(lrow + 64) * K + k0 + lk4);

        __syncthreads();   // previous compute finished before overwriting tiles
        As[lk4+0][lrow]    = a0.x; As[lk4+1][lrow]    = a0.y;
        As[lk4+2][lrow]    = a0.z; As[lk4+3][lrow]    = a0.w;
        As[lk4+0][lrow+64] = a1.x; As[lk4+1][lrow+64] = a1.y;
        As[lk4+2][lrow+64] = a1.z; As[lk4+3][lrow+64] = a1.w;
        Bs[lk4+0][lrow]    = b0.x; Bs[lk4+1][lrow]    = b0.y;
        Bs[lk4+2][lrow]    = b0.z; Bs[lk4+3][lrow]    = b0.w;
        Bs[lk4+0][lrow+64] = b1.x; Bs[lk4+1][lrow+64] = b1.y;
        Bs[lk4+2][lrow+64] = b1.z; Bs[lk4+3][lrow+64] = b1.w;
        __syncthreads();

#pragma unroll
        for (int k = 0; k < 16; k++) {
            float a[8], b[8];
            float4 av0 = *(const float4*)&As[k][ty*4];
            float4 av1 = *(const float4*)&As[k][ty*4 + 64];
            float4 bv0 = *(const float4*)&Bs[k][tx*4];
            float4 bv1 = *(const float4*)&Bs[k][tx*4 + 64];
            a[0]=av0.x; a[1]=av0.y; a[2]=av0.z; a[3]=av0.w;
            a[4]=av1.x; a[5]=av1.y; a[6]=av1.z; a[7]=av1.w;
            b[0]=bv0.x; b[1]=bv0.y; b[2]=bv0.z; b[3]=bv0.w;
            b[4]=bv1.x; b[5]=bv1.y; b[6]=bv1.z; b[7]=bv1.w;
#pragma unroll
            for (int i = 0; i < 8; i++)
#pragma unroll
                for (int j = 0; j < 8; j++)
                    acc[i][j] = fmaf(a[i], b[j], acc[i][j]);
        }
    }

#pragma unroll
    for (int i = 0; i < 8; i++) {
        int row = bm + ((i < 4) ? (ty*4 + i) : (64 + ty*4 + (i - 4)));
        float* cp = C + (size_t)row * N + bn;
        *(float4*)(cp + tx*4)      = make_float4(acc[i][0], acc[i][1], acc[i][2], acc[i][3]);
        *(float4*)(cp + 64 + tx*4) = make_float4(acc[i][4], acc[i][5], acc[i][6], acc[i][7]);
    }
}

// =====================================================================
// Flash-style sliding-window attention.
// Q,K,V laid out [B*S, H*D] (row stride DIM). One block = (b, h, 64-row q tile).
// Online softmax over kv tiles of 64 up to j <= i + 128.
// =====================================================================
#define QKS 68     // padded stride for transposed Qt/Kt  [d][r]
#define VPS 132    // padded stride for Vs / Ps           [r][c]

__global__ __launch_bounds__(256, 1)
void attn_kernel(const float* __restrict__ Q, const float* __restrict__ K,
                 const float* __restrict__ V, float* __restrict__ O)
{
    extern __shared__ float sm[];
    float* Qt = sm;                  // [128][QKS]  Qt[d*QKS + r]
    float* Kt = Qt + 128 * QKS;      // [128][QKS]
    float* Vs = Kt + 128 * QKS;      // [64][VPS]   Vs[r*VPS + c]
    float* Ps = Vs + 64  * VPS;      // [64][VPS]

    const int tid  = threadIdx.x;
    const int tx   = tid & 15;
    const int ty   = tid >> 4;
    const int warp = tid >> 5;
    const int lane = tid & 31;

    const int qt = blockIdx.x;       // 0..31
    const int h  = blockIdx.y;       // 0..15
    const int b  = blockIdx.z;       // 0..1
    const int q0 = qt * 64;

    const float scale = 0.08838834764831845f; // 1/sqrt(128)

    // ---- load Q tile transposed: Qt[d][r] ----
    for (int r = warp; r < 64; r += 8) {
        const float* src = Q + (size_t)(b*SEQ + q0 + r) * DIM + h * HDIM;
        float v0 = src[lane], v1 = src[lane+32], v2 = src[lane+64], v3 = src[lane+96];
        Qt[(lane     ) * QKS + r] = v0;
        Qt[(lane + 32) * QKS + r] = v1;
        Qt[(lane + 64) * QKS + r] = v2;
        Qt[(lane + 96) * QKS + r] = v3;
    }

    float m[4], l[4];
    float acc[4][8];
#pragma unroll
    for (int i = 0; i < 4; i++) {
        m[i] = -1e30f; l[i] = 0.f;
#pragma unroll
        for (int c = 0; c < 8; c++) acc[i][c] = 0.f;
    }

    const int nkv = min(32, qt + 3);   // kv tiles needed: j <= q0+63+128

    for (int kb = 0; kb < nkv; kb++) {
        const int kv0 = kb * 64;
        __syncthreads();   // previous PV reads of Kt/Vs/Ps done

        // ---- load K transposed, V natural ----
        for (int r = warp; r < 64; r += 8) {
            const float* ks = K + (size_t)(b*SEQ + kv0 + r) * DIM + h * HDIM;
            float v0 = ks[lane], v1 = ks[lane+32], v2 = ks[lane+64], v3 = ks[lane+96];
            Kt[(lane     ) * QKS + r] = v0;
            Kt[(lane + 32) * QKS + r] = v1;
            Kt[(lane + 64) * QKS + r] = v2;
            Kt[(lane + 96) * QKS + r] = v3;
            const float* vsrc = V + (size_t)(b*SEQ + kv0 + r) * DIM + h * HDIM;
            float4 vv = *(const float4*)(vsrc + lane * 4);
            *(float4*)&Vs[r * VPS + lane * 4] = vv;
        }
        __syncthreads();

        // ---- S = Q K^T (64x64), thread owns S[4ty+i][4tx+j] ----
        float s[4][4];
#pragma unroll
        for (int i = 0; i < 4; i++)
#pragma unroll
            for (int j = 0; j < 4; j++) s[i][j] = 0.f;

#pragma unroll 4
        for (int d = 0; d < 128; d++) {
            float4 qv = *(const float4*)&Qt[d * QKS + 4*ty];
            float4 kv = *(const float4*)&Kt[d * QKS + 4*tx];
            float qa[4] = {qv.x, qv.y, qv.z, qv.w};
            float ka[4] = {kv.x, kv.y, kv.z, kv.w};
#pragma unroll
            for (int i = 0; i < 4; i++)
#pragma unroll
                for (int j = 0; j < 4; j++)
                    s[i][j] = fmaf(qa[i], ka[j], s[i][j]);
        }

        // ---- mask + online softmax ----
        const int qi_base = q0 + 4*ty;
        const int kj_base = kv0 + 4*tx;
#pragma unroll
        for (int i = 0; i < 4; i++) {
            float rmax = -1e30f;
#pragma unroll
            for (int j = 0; j < 4; j++) {
                float val = s[i][j] * scale;
                if ((kj_base + j) - (qi_base + i) > WINHALF) val = -1e30f;
                s[i][j] = val;
                rmax = fmaxf(rmax, val);
            }
#pragma unroll
            for (int off = 8; off > 0; off >>= 1)
                rmax = fmaxf(rmax, __shfl_xor_sync(0xffffffffu, rmax, off));

            float mnew  = fmaxf(m[i], rmax);
            float alpha = __expf(m[i] - mnew);
            float rs = 0.f;
#pragma unroll
            for (int j = 0; j < 4; j++) {
                float p = __expf(s[i][j] - mnew);
                s[i][j] = p;
                rs += p;
            }
#pragma unroll
            for (int off = 8; off > 0; off >>= 1)
                rs += __shfl_xor_sync(0xffffffffu, rs, off);

            l[i] = l[i] * alpha + rs;
            m[i] = mnew;
#pragma unroll
            for (int c = 0; c < 8; c++) acc[i][c] *= alpha;

            *(float4*)&Ps[(4*ty + i) * VPS + 4*tx] =
                make_float4(s[i][0], s[i][1], s[i][2], s[i][3]);
        }
        __syncthreads();

        // ---- O += P V : thread owns rows 4ty+i, d-cols 8tx..8tx+7 ----
#pragma unroll 2
        for (int j = 0; j < 64; j++) {
            float4 v0 = *(const float4*)&Vs[j * VPS + 8*tx];
            float4 v1 = *(const float4*)&Vs[j * VPS + 8*tx + 4];
#pragma unroll
            for (int i = 0; i < 4; i++) {
                float p = Ps[(4*ty + i) * VPS + j];
                acc[i][0] = fmaf(p, v0.x, acc[i][0]);
                acc[i][1] = fmaf(p, v0.y, acc[i][1]);
                acc[i][2] = fmaf(p, v0.z, acc[i][2]);
                acc[i][3] = fmaf(p, v0.w, acc[i][3]);
                acc[i][4] = fmaf(p, v1.x, acc[i][4]);
                acc[i][5] = fmaf(p, v1.y, acc[i][5]);
                acc[i][6] = fmaf(p, v1.z, acc[i][6]);
                acc[i][7] = fmaf(p, v1.w, acc[i][7]);
            }
        }
    }

    // ---- normalize and write out [B*S, H*D] ----
#pragma unroll
    for (int i = 0; i < 4; i++) {
        float inv = 1.0f / l[i];
        float* op = O + (size_t)(b*SEQ + q0 + 4*ty + i) * DIM + h * HDIM + 8*tx;
        *(float4*)(op)     = make_float4(acc[i][0]*inv, acc[i][1]*inv,
                                         acc[i][2]*inv, acc[i][3]*inv);
        *(float4*)(op + 4) = make_float4(acc[i][4]*inv, acc[i][5]*inv,
                                         acc[i][6]*inv, acc[i][7]*inv);
    }
}

// =====================================================================
// launch
// =====================================================================
extern "C" void kernel_launch(void* const* d_in, const int* in_sizes, int n_in,
                              void* d_out, int out_size)
{
    const float* x  = (const float*)d_in[0];
    const float* wq = (const float*)d_in[1];
    const float* wk = (const float*)d_in[2];
    const float* wv = (const float*)d_in[3];
    const float* wo = (const float*)d_in[4];
    float* out = (float*)d_out;

    float *q, *k, *v, *ao;
    cudaGetSymbolAddress((void**)&q,  g_q);
    cudaGetSymbolAddress((void**)&k,  g_k);
    cudaGetSymbolAddress((void**)&v,  g_v);
    cudaGetSymbolAddress((void**)&ao, g_ao);

    const int ATT_SMEM = (128*QKS*2 + 64*VPS*2) * (int)sizeof(float); // 137216 B
    cudaFuncSetAttribute(attn_kernel, cudaFuncAttributeMaxDynamicSharedMemorySize, ATT_SMEM);

    dim3 gemm_grid(DIM/128, MROWS/128);   // (16, 32)
    sgemm_nt<<<gemm_grid, 256>>>(x, wq, q, MROWS, DIM, DIM);
    sgemm_nt<<<gemm_grid, 256>>>(x, wk, k, MROWS, DIM, DIM);
    sgemm_nt<<<gemm_grid, 256>>>(x, wv, v, MROWS, DIM, DIM);

    dim3 att_grid(SEQ/64, NHEADS, BATCH); // (32, 16, 2)
    attn_kernel<<<att_grid, 256, ATT_SMEM>>>(q, k, v, ao);

    sgemm_nt<<<gemm_grid, 256>>>(ao, wo, out, MROWS, DIM, DIM);
}

// round 3
// speedup vs baseline: 1.6746x; 1.6746x over previous
#include <cuda_runtime.h>
#include <cuda_bf16.h>
#include <math.h>
#include <stdint.h>

// Problem constants
#define DIM     2048
#define NHEADS  16
#define HDIM    128
#define BATCH   2
#define SEQ     2048
#define MROWS   (BATCH*SEQ)     // 4096
#define WINHALF 128             // allowed: j - i <= 128

// ---------------- scratch (device globals: no allocation allowed) -------------
__device__ float g_q [MROWS*DIM];
__device__ float g_k [MROWS*DIM];
__device__ float g_v [MROWS*DIM];
__device__ float g_ao[MROWS*DIM];

__device__ __nv_bfloat16 g_xh [MROWS*DIM];
__device__ __nv_bfloat16 g_xl [MROWS*DIM];
__device__ __nv_bfloat16 g_wh [4*DIM*DIM];   // wq, wk, wv, wo (hi)
__device__ __nv_bfloat16 g_wl [4*DIM*DIM];   // (lo)
__device__ __nv_bfloat16 g_aoh[MROWS*DIM];
__device__ __nv_bfloat16 g_aol[MROWS*DIM];

// =====================================================================
// low-level helpers (base ISA only: sm_80/sm_90 non-'a' features)
// =====================================================================
__device__ __forceinline__ uint32_t smem_u32(const void* p) {
    uint32_t a;
    asm("{ .reg .u64 t; cvta.to.shared.u64 t, %1; cvt.u32.u64 %0, t; }"
        : "=r"(a) : "l"(p));
    return a;
}
__device__ __forceinline__ void cp_async16(uint32_t d, const void* g) {
    uint64_t ga = (uint64_t)__cvta_generic_to_global(g);
    asm volatile("cp.async.cg.shared.global [%0], [%1], 16;" :: "r"(d), "l"(ga));
}
__device__ __forceinline__ void cp_commit() {
    asm volatile("cp.async.commit_group;" ::: "memory");
}
template<int N> __device__ __forceinline__ void cp_wait() {
    asm volatile("cp.async.wait_group %0;" :: "n"(N) : "memory");
}
__device__ __forceinline__ void ldsm4(uint32_t& r0, uint32_t& r1,
                                      uint32_t& r2, uint32_t& r3, uint32_t a) {
    asm volatile("ldmatrix.sync.aligned.m8n8.x4.shared.b16 {%0,%1,%2,%3}, [%4];"
                 : "=r"(r0), "=r"(r1), "=r"(r2), "=r"(r3) : "r"(a));
}
__device__ __forceinline__ void mma16816(float* d, const uint32_t* a, const uint32_t* b) {
    asm volatile(
        "mma.sync.aligned.m16n8k16.row.col.f32.bf16.bf16.f32 "
        "{%0,%1,%2,%3}, {%4,%5,%6,%7}, {%8,%9}, {%0,%1,%2,%3};"
        : "+f"(d[0]), "+f"(d[1]), "+f"(d[2]), "+f"(d[3])
        : "r"(a[0]), "r"(a[1]), "r"(a[2]), "r"(a[3]), "r"(b[0]), "r"(b[1]));
}

// =====================================================================
// Split fp32 -> (hi, lo) bf16
// =====================================================================
__global__ void split_kernel(const float* __restrict__ src,
                             __nv_bfloat16* __restrict__ hi,
                             __nv_bfloat16* __restrict__ lo, int n4)
{
    int i = blockIdx.x * blockDim.x + threadIdx.x;
    if (i >= n4) return;
    float4 v = ((const float4*)src)[i];
    __nv_bfloat16 h0 = __float2bfloat16(v.x);
    __nv_bfloat16 h1 = __float2bfloat16(v.y);
    __nv_bfloat16 h2 = __float2bfloat16(v.z);
    __nv_bfloat16 h3 = __float2bfloat16(v.w);
    __nv_bfloat16 l0 = __float2bfloat16(v.x - __bfloat162float(h0));
    __nv_bfloat16 l1 = __float2bfloat16(v.y - __bfloat162float(h1));
    __nv_bfloat16 l2 = __float2bfloat16(v.z - __bfloat162float(h2));
    __nv_bfloat16 l3 = __float2bfloat16(v.w - __bfloat162float(h3));
    __nv_bfloat162 hA = __halves2bfloat162(h0, h1), hB = __halves2bfloat162(h2, h3);
    __nv_bfloat162 lA = __halves2bfloat162(l0, l1), lB = __halves2bfloat162(l2, l3);
    uint2 ph, pl;
    ph.x = *(uint32_t*)&hA; ph.y = *(uint32_t*)&hB;
    pl.x = *(uint32_t*)&lA; pl.y = *(uint32_t*)&lB;
    ((uint2*)hi)[i] = ph;
    ((uint2*)lo)[i] = pl;
}

// =====================================================================
// HMMA GEMM:  C[M,N] = Ah*Bh^T + Ah*Bl^T + Al*Bh^T
// A* : [4096, 2048] bf16 K-major.  B* : [2048, 2048] bf16 K-major.
// CTA tile 128x128, BK=64, 3-stage cp.async pipeline, 8 warps (32x64 each).
// =====================================================================
#define GBM     128
#define GBN     128
#define GBK     64
#define GSTAGES 3
#define GASTG   16384                  // 128 rows x 128 bytes
#define GSTG    (2*GASTG)
#define GSMEM   (GSTAGES*GSTG)         // 98304
#define GNIT    96                     // 3 passes x 32 k-chunks

__global__ __launch_bounds__(256, 2)
void gemm_mma(const __nv_bfloat16* __restrict__ Ah, const __nv_bfloat16* __restrict__ Al,
              const __nv_bfloat16* __restrict__ Bh, const __nv_bfloat16* __restrict__ Bl,
              float* __restrict__ C)
{
    extern __shared__ __align__(128) char gsm[];
    const uint32_t smb = smem_u32(gsm);

    const int tid  = threadIdx.x;
    const int lane = tid & 31;
    const int warp = tid >> 5;
    const int wm   = warp >> 1;        // 0..3
    const int wn   = warp & 1;         // 0..1
    const int bm   = blockIdx.y * GBM;
    const int bn   = blockIdx.x * GBN;

    // ldmatrix per-lane addressing precompute
    const int lr  = lane & 15;         // row within a 16-row tile
    const int hi  = lane >> 4;         // 0: k 0-7, 1: k 8-15 (16B chunk halves)
    const int rsw = lr & 7;            // swizzle xor term (tile bases are mult of 8)
    uint32_t aRow[2], bRow[4];
#pragma unroll
    for (int mt = 0; mt < 2; mt++) aRow[mt] = (uint32_t)(wm*32 + mt*16 + lr) * 128;
#pragma unroll
    for (int bt = 0; bt < 4; bt++) bRow[bt] = GASTG + (uint32_t)(wn*64 + bt*16 + lr) * 128;

    // loader precompute: thread handles 4 chunks of A and 4 of B per stage
    int ldr[4], ldc[4];
#pragma unroll
    for (int i = 0; i < 4; i++) {
        int id = tid + 256*i;
        ldr[i] = id >> 3;              // row 0..127
        ldc[i] = id & 7;               // 16B chunk 0..7
    }

    float acc[2][8][4];
#pragma unroll
    for (int mt = 0; mt < 2; mt++)
#pragma unroll
        for (int nt = 0; nt < 8; nt++)
#pragma unroll
            for (int e = 0; e < 4; e++) acc[mt][nt][e] = 0.f;

    // stage loader
    auto load_stage = [&](int it) {
        if (it >= GNIT) return;
        const int pass = it >> 5;
        const int k0   = (it & 31) * GBK;
        const __nv_bfloat16* Aop = (pass < 2)  ? Ah : Al;
        const __nv_bfloat16* Bop = (pass == 1) ? Bl : Bh;
        const uint32_t sb = smb + (uint32_t)(it % GSTAGES) * GSTG;
#pragma unroll
        for (int i = 0; i < 4; i++) {
            const int r = ldr[i], c = ldc[i];
            const uint32_t dof = (uint32_t)r * 128 + (uint32_t)((c ^ (r & 7)) << 4);
            cp_async16(sb + dof,         Aop + (size_t)(bm + r) * DIM + k0 + c*8);
            cp_async16(sb + GASTG + dof, Bop + (size_t)(bn + r) * DIM + k0 + c*8);
        }
    };

    load_stage(0); cp_commit();
    load_stage(1); cp_commit();

    for (int it = 0; it < GNIT; it++) {
        cp_wait<1>();
        __syncthreads();

        load_stage(it + 2); cp_commit();

        const uint32_t sb = smb + (uint32_t)(it % GSTAGES) * GSTG;
#pragma unroll
        for (int ks = 0; ks < 4; ks++) {
            const uint32_t cz = (uint32_t)(((2*ks + hi) ^ rsw) << 4);
            uint32_t a[2][4];
            ldsm4(a[0][0], a[0][1], a[0][2], a[0][3], sb + aRow[0] + cz);
            ldsm4(a[1][0], a[1][1], a[1][2], a[1][3], sb + aRow[1] + cz);
            uint32_t b[8][2];
#pragma unroll
            for (int bt = 0; bt < 4; bt++) {
                uint32_t r0, r1, r2, r3;
                ldsm4(r0, r1, r2, r3, sb + bRow[bt] + cz);
                b[2*bt+0][0] = r0; b[2*bt+0][1] = r2;
                b[2*bt+1][0] = r1; b[2*bt+1][1] = r3;
            }
#pragma unroll
            for (int mt = 0; mt < 2; mt++)
#pragma unroll
                for (int nt = 0; nt < 8; nt++)
                    mma16816(acc[mt][nt], a[mt], b[nt]);
        }
    }

    // epilogue: direct fp32 stores
    const int er = lane >> 2;
    const int ec = (lane & 3) * 2;
#pragma unroll
    for (int mt = 0; mt < 2; mt++) {
#pragma unroll
        for (int nt = 0; nt < 8; nt++) {
            const int row = bm + wm*32 + mt*16 + er;
            const int col = bn + wn*64 + nt*8 + ec;
            *(float2*)&C[(size_t)row       * DIM + col] = make_float2(acc[mt][nt][0], acc[mt][nt][1]);
            *(float2*)&C[(size_t)(row + 8) * DIM + col] = make_float2(acc[mt][nt][2], acc[mt][nt][3]);
        }
    }
}

// =====================================================================
// Flash-style sliding-window attention (fp32, known-good from R1)
// =====================================================================
#define QKS 68
#define VPS 132

__global__ __launch_bounds__(256, 1)
void attn_kernel(const float* __restrict__ Q, const float* __restrict__ K,
                 const float* __restrict__ V, float* __restrict__ O)
{
    extern __shared__ float sm[];
    float* Qt = sm;
    float* Kt = Qt + 128 * QKS;
    float* Vs = Kt + 128 * QKS;
    float* Ps = Vs + 64  * VPS;

    const int tid  = threadIdx.x;
    const int tx   = tid & 15;
    const int ty   = tid >> 4;
    const int warp = tid >> 5;
    const int lane = tid & 31;

    const int qt = blockIdx.x;
    const int h  = blockIdx.y;
    const int b  = blockIdx.z;
    const int q0 = qt * 64;

    const float scale = 0.08838834764831845f;

    for (int r = warp; r < 64; r += 8) {
        const float* src = Q + (size_t)(b*SEQ + q0 + r) * DIM + h * HDIM;
        float v0 = src[lane], v1 = src[lane+32], v2 = src[lane+64], v3 = src[lane+96];
        Qt[(lane     ) * QKS + r] = v0;
        Qt[(lane + 32) * QKS + r] = v1;
        Qt[(lane + 64) * QKS + r] = v2;
        Qt[(lane + 96) * QKS + r] = v3;
    }

    float m[4], l[4];
    float acc[4][8];
#pragma unroll
    for (int i = 0; i < 4; i++) {
        m[i] = -1e30f; l[i] = 0.f;
#pragma unroll
        for (int c = 0; c < 8; c++) acc[i][c] = 0.f;
    }

    const int nkv = min(32, qt + 3);

    for (int kb = 0; kb < nkv; kb++) {
        const int kv0 = kb * 64;
        __syncthreads();

        for (int r = warp; r < 64; r += 8) {
            const float* ks = K + (size_t)(b*SEQ + kv0 + r) * DIM + h * HDIM;
            float v0 = ks[lane], v1 = ks[lane+32], v2 = ks[lane+64], v3 = ks[lane+96];
            Kt[(lane     ) * QKS + r] = v0;
            Kt[(lane + 32) * QKS + r] = v1;
            Kt[(lane + 64) * QKS + r] = v2;
            Kt[(lane + 96) * QKS + r] = v3;
            const float* vsrc = V + (size_t)(b*SEQ + kv0 + r) * DIM + h * HDIM;
            float4 vv = *(const float4*)(vsrc + lane * 4);
            *(float4*)&Vs[r * VPS + lane * 4] = vv;
        }
        __syncthreads();

        float s[4][4];
#pragma unroll
        for (int i = 0; i < 4; i++)
#pragma unroll
            for (int j = 0; j < 4; j++) s[i][j] = 0.f;

#pragma unroll 4
        for (int d = 0; d < 128; d++) {
            float4 qv = *(const float4*)&Qt[d * QKS + 4*ty];
            float4 kv = *(const float4*)&Kt[d * QKS + 4*tx];
            float qa[4] = {qv.x, qv.y, qv.z, qv.w};
            float ka[4] = {kv.x, kv.y, kv.z, kv.w};
#pragma unroll
            for (int i = 0; i < 4; i++)
#pragma unroll
                for (int j = 0; j < 4; j++)
                    s[i][j] = fmaf(qa[i], ka[j], s[i][j]);
        }

        const int qi_base = q0 + 4*ty;
        const int kj_base = kv0 + 4*tx;
#pragma unroll
        for (int i = 0; i < 4; i++) {
            float rmax = -1e30f;
#pragma unroll
            for (int j = 0; j < 4; j++) {
                float val = s[i][j] * scale;
                if ((kj_base + j) - (qi_base + i) > WINHALF) val = -1e30f;
                s[i][j] = val;
                rmax = fmaxf(rmax, val);
            }
#pragma unroll
            for (int off = 8; off > 0; off >>= 1)
                rmax = fmaxf(rmax, __shfl_xor_sync(0xffffffffu, rmax, off));

            float mnew  = fmaxf(m[i], rmax);
            float alpha = __expf(m[i] - mnew);
            float rs = 0.f;
#pragma unroll
            for (int j = 0; j < 4; j++) {
                float p = __expf(s[i][j] - mnew);
                s[i][j] = p;
                rs += p;
            }
#pragma unroll
            for (int off = 8; off > 0; off >>= 1)
                rs += __shfl_xor_sync(0xffffffffu, rs, off);

            l[i] = l[i] * alpha + rs;
            m[i] = mnew;
#pragma unroll
            for (int c = 0; c < 8; c++) acc[i][c] *= alpha;

            *(float4*)&Ps[(4*ty + i) * VPS + 4*tx] =
                make_float4(s[i][0], s[i][1], s[i][2], s[i][3]);
        }
        __syncthreads();

#pragma unroll 2
        for (int j = 0; j < 64; j++) {
            float4 v0 = *(const float4*)&Vs[j * VPS + 8*tx];
            float4 v1 = *(const float4*)&Vs[j * VPS + 8*tx + 4];
#pragma unroll
            for (int i = 0; i < 4; i++) {
                float p = Ps[(4*ty + i) * VPS + j];
                acc[i][0] = fmaf(p, v0.x, acc[i][0]);
                acc[i][1] = fmaf(p, v0.y, acc[i][1]);
                acc[i][2] = fmaf(p, v0.z, acc[i][2]);
                acc[i][3] = fmaf(p, v0.w, acc[i][3]);
                acc[i][4] = fmaf(p, v1.x, acc[i][4]);
                acc[i][5] = fmaf(p, v1.y, acc[i][5]);
                acc[i][6] = fmaf(p, v1.z, acc[i][6]);
                acc[i][7] = fmaf(p, v1.w, acc[i][7]);
            }
        }
    }

#pragma unroll
    for (int i = 0; i < 4; i++) {
        float inv = 1.0f / l[i];
        float* op = O + (size_t)(b*SEQ + q0 + 4*ty + i) * DIM + h * HDIM + 8*tx;
        *(float4*)(op)     = make_float4(acc[i][0]*inv, acc[i][1]*inv,
                                         acc[i][2]*inv, acc[i][3]*inv);
        *(float4*)(op + 4) = make_float4(acc[i][4]*inv, acc[i][5]*inv,
                                         acc[i][6]*inv, acc[i][7]*inv);
    }
}

// =====================================================================
// Host launch
// =====================================================================
extern "C" void kernel_launch(void* const* d_in, const int* in_sizes, int n_in,
                              void* d_out, int out_size)
{
    const float* x  = (const float*)d_in[0];
    const float* wq = (const float*)d_in[1];
    const float* wk = (const float*)d_in[2];
    const float* wv = (const float*)d_in[3];
    const float* wo = (const float*)d_in[4];
    float* out = (float*)d_out;

    float *q, *k, *v, *ao;
    __nv_bfloat16 *xh, *xl, *wh, *wl, *aoh, *aol;
    cudaGetSymbolAddress((void**)&q,   g_q);
    cudaGetSymbolAddress((void**)&k,   g_k);
    cudaGetSymbolAddress((void**)&v,   g_v);
    cudaGetSymbolAddress((void**)&ao,  g_ao);
    cudaGetSymbolAddress((void**)&xh,  g_xh);
    cudaGetSymbolAddress((void**)&xl,  g_xl);
    cudaGetSymbolAddress((void**)&wh,  g_wh);
    cudaGetSymbolAddress((void**)&wl,  g_wl);
    cudaGetSymbolAddress((void**)&aoh, g_aoh);
    cudaGetSymbolAddress((void**)&aol, g_aol);

    const int ATT_SMEM = (128*QKS*2 + 64*VPS*2) * (int)sizeof(float);
    cudaFuncSetAttribute(attn_kernel, cudaFuncAttributeMaxDynamicSharedMemorySize, ATT_SMEM);
    cudaFuncSetAttribute(gemm_mma,    cudaFuncAttributeMaxDynamicSharedMemorySize, GSMEM);

    // ---- splits ----
    split_kernel<<<(MROWS*DIM/4 + 255)/256, 256>>>(x, xh, xl, MROWS*DIM/4);
    const float* ws[4] = {wq, wk, wv, wo};
    for (int i = 0; i < 4; i++)
        split_kernel<<<(DIM*DIM/4 + 255)/256, 256>>>(ws[i],
            wh + (size_t)i * DIM * DIM, wl + (size_t)i * DIM * DIM, DIM*DIM/4);

    // ---- projections on tensor cores (HMMA) ----
    dim3 gg(DIM/128, MROWS/128);     // (16, 32)
    gemm_mma<<<gg, 256, GSMEM>>>(xh, xl, wh + 0*(size_t)DIM*DIM, wl + 0*(size_t)DIM*DIM, q);
    gemm_mma<<<gg, 256, GSMEM>>>(xh, xl, wh + 1*(size_t)DIM*DIM, wl + 1*(size_t)DIM*DIM, k);
    gemm_mma<<<gg, 256, GSMEM>>>(xh, xl, wh + 2*(size_t)DIM*DIM, wl + 2*(size_t)DIM*DIM, v);

    // ---- attention ----
    dim3 att_grid(SEQ/64, NHEADS, BATCH);
    attn_kernel<<<att_grid, 256, ATT_SMEM>>>(q, k, v, ao);

    // ---- output projection ----
    split_kernel<<<(MROWS*DIM/4 + 255)/256, 256>>>(ao, aoh, aol, MROWS*DIM/4);
    gemm_mma<<<gg, 256, GSMEM>>>(aoh, aol, wh + 3*(size_t)DIM*DIM, wl + 3*(size_t)DIM*DIM, out);
}

// round 4
// speedup vs baseline: 2.4280x; 1.4499x over previous
#include <cuda_runtime.h>
#include <cuda_bf16.h>
#include <math.h>
#include <stdint.h>

// Problem constants
#define DIM     2048
#define NHEADS  16
#define HDIM    128
#define BATCH   2
#define SEQ     2048
#define MROWS   (BATCH*SEQ)     // 4096
#define WINHALF 128             // allowed: j - i <= 128
#define SCALE   0.08838834764831845f

// ---------------- scratch (device globals: no allocation allowed) -------------
__device__ __nv_bfloat16 g_xh [MROWS*DIM];
__device__ __nv_bfloat16 g_xl [MROWS*DIM];
__device__ __nv_bfloat16 g_wh [4*DIM*DIM];
__device__ __nv_bfloat16 g_wl [4*DIM*DIM];
__device__ __nv_bfloat16 g_qh [MROWS*DIM];
__device__ __nv_bfloat16 g_ql [MROWS*DIM];
__device__ __nv_bfloat16 g_kh [MROWS*DIM];
__device__ __nv_bfloat16 g_kl [MROWS*DIM];
__device__ __nv_bfloat16 g_vh [MROWS*DIM];
__device__ __nv_bfloat16 g_vl [MROWS*DIM];
__device__ __nv_bfloat16 g_aoh[MROWS*DIM];
__device__ __nv_bfloat16 g_aol[MROWS*DIM];

// =====================================================================
// low-level helpers (base ISA only)
// =====================================================================
__device__ __forceinline__ uint32_t smem_u32(const void* p) {
    uint32_t a;
    asm("{ .reg .u64 t; cvta.to.shared.u64 t, %1; cvt.u32.u64 %0, t; }"
        : "=r"(a) : "l"(p));
    return a;
}
__device__ __forceinline__ void cp_async16(uint32_t d, const void* g) {
    uint64_t ga = (uint64_t)__cvta_generic_to_global(g);
    asm volatile("cp.async.cg.shared.global [%0], [%1], 16;" :: "r"(d), "l"(ga));
}
__device__ __forceinline__ void cp_commit() {
    asm volatile("cp.async.commit_group;" ::: "memory");
}
template<int N> __device__ __forceinline__ void cp_wait() {
    asm volatile("cp.async.wait_group %0;" :: "n"(N) : "memory");
}
__device__ __forceinline__ void ldsm4(uint32_t& r0, uint32_t& r1,
                                      uint32_t& r2, uint32_t& r3, uint32_t a) {
    asm volatile("ldmatrix.sync.aligned.m8n8.x4.shared.b16 {%0,%1,%2,%3}, [%4];"
                 : "=r"(r0), "=r"(r1), "=r"(r2), "=r"(r3) : "r"(a));
}
__device__ __forceinline__ void ldsm4t(uint32_t& r0, uint32_t& r1,
                                       uint32_t& r2, uint32_t& r3, uint32_t a) {
    asm volatile("ldmatrix.sync.aligned.m8n8.x4.trans.shared.b16 {%0,%1,%2,%3}, [%4];"
                 : "=r"(r0), "=r"(r1), "=r"(r2), "=r"(r3) : "r"(a));
}
__device__ __forceinline__ void mma16816(float* d, const uint32_t* a, const uint32_t* b) {
    asm volatile(
        "mma.sync.aligned.m16n8k16.row.col.f32.bf16.bf16.f32 "
        "{%0,%1,%2,%3}, {%4,%5,%6,%7}, {%8,%9}, {%0,%1,%2,%3};"
        : "+f"(d[0]), "+f"(d[1]), "+f"(d[2]), "+f"(d[3])
        : "r"(a[0]), "r"(a[1]), "r"(a[2]), "r"(a[3]), "r"(b[0]), "r"(b[1]));
}
__device__ __forceinline__ void split2(float a, float b, uint32_t& hp, uint32_t& lp) {
    __nv_bfloat16 ha = __float2bfloat16(a), hb = __float2bfloat16(b);
    float ra = a - __bfloat162float(ha);
    float rb = b - __bfloat162float(hb);
    __nv_bfloat162 h = __halves2bfloat162(ha, hb);
    __nv_bfloat162 l = __halves2bfloat162(__float2bfloat16(ra), __float2bfloat16(rb));
    hp = *(uint32_t*)&h;
    lp = *(uint32_t*)&l;
}

// =====================================================================
// Split fp32 -> (hi, lo) bf16
// =====================================================================
__global__ void split_kernel(const float* __restrict__ src,
                             __nv_bfloat16* __restrict__ hi,
                             __nv_bfloat16* __restrict__ lo, int n4)
{
    int i = blockIdx.x * blockDim.x + threadIdx.x;
    if (i >= n4) return;
    float4 v = ((const float4*)src)[i];
    uint32_t h0, l0, h1, l1;
    split2(v.x, v.y, h0, l0);
    split2(v.z, v.w, h1, l1);
    ((uint2*)hi)[i] = make_uint2(h0, h1);
    ((uint2*)lo)[i] = make_uint2(l0, l1);
}

// =====================================================================
// HMMA GEMM:  C = mul * (Ah*Bh^T + Ah*Bl^T + Al*Bh^T)
// CTA tile 128x128, BK=64, 3-stage cp.async pipeline, 8 warps (32x64 each).
// SPLIT=false: fp32 out.  SPLIT=true: bf16 hi/lo out.
// =====================================================================
#define GBM     128
#define GBN     128
#define GBK     64
#define GSTAGES 3
#define GASTG   16384
#define GSTG    (2*GASTG)
#define GSMEM   (GSTAGES*GSTG)
#define GNIT    96

template<bool SPLIT>
__global__ __launch_bounds__(256, 2)
void gemm_mma(const __nv_bfloat16* __restrict__ Ah, const __nv_bfloat16* __restrict__ Al,
              const __nv_bfloat16* __restrict__ Bh, const __nv_bfloat16* __restrict__ Bl,
              float* __restrict__ C,
              __nv_bfloat16* __restrict__ Ch, __nv_bfloat16* __restrict__ Cl,
              float mul)
{
    extern __shared__ __align__(128) char gsm[];
    const uint32_t smb = smem_u32(gsm);

    const int tid  = threadIdx.x;
    const int lane = tid & 31;
    const int warp = tid >> 5;
    const int wm   = warp >> 1;
    const int wn   = warp & 1;
    const int bm   = blockIdx.y * GBM;
    const int bn   = blockIdx.x * GBN;

    const int lr  = lane & 15;
    const int hi  = lane >> 4;
    const int rsw = lr & 7;
    uint32_t aRow[2], bRow[4];
#pragma unroll
    for (int mt = 0; mt < 2; mt++) aRow[mt] = (uint32_t)(wm*32 + mt*16 + lr) * 128;
#pragma unroll
    for (int bt = 0; bt < 4; bt++) bRow[bt] = GASTG + (uint32_t)(wn*64 + bt*16 + lr) * 128;

    int ldr[4], ldc[4];
#pragma unroll
    for (int i = 0; i < 4; i++) {
        int id = tid + 256*i;
        ldr[i] = id >> 3;
        ldc[i] = id & 7;
    }

    float acc[2][8][4];
#pragma unroll
    for (int mt = 0; mt < 2; mt++)
#pragma unroll
        for (int nt = 0; nt < 8; nt++)
#pragma unroll
            for (int e = 0; e < 4; e++) acc[mt][nt][e] = 0.f;

    auto load_stage = [&](int it) {
        if (it >= GNIT) return;
        const int pass = it >> 5;
        const int k0   = (it & 31) * GBK;
        const __nv_bfloat16* Aop = (pass < 2)  ? Ah : Al;
        const __nv_bfloat16* Bop = (pass == 1) ? Bl : Bh;
        const uint32_t sb = smb + (uint32_t)(it % GSTAGES) * GSTG;
#pragma unroll
        for (int i = 0; i < 4; i++) {
            const int r = ldr[i], c = ldc[i];
            const uint32_t dof = (uint32_t)r * 128 + (uint32_t)((c ^ (r & 7)) << 4);
            cp_async16(sb + dof,         Aop + (size_t)(bm + r) * DIM + k0 + c*8);
            cp_async16(sb + GASTG + dof, Bop + (size_t)(bn + r) * DIM + k0 + c*8);
        }
    };

    load_stage(0); cp_commit();
    load_stage(1); cp_commit();

    for (int it = 0; it < GNIT; it++) {
        cp_wait<1>();
        __syncthreads();

        load_stage(it + 2); cp_commit();

        const uint32_t sb = smb + (uint32_t)(it % GSTAGES) * GSTG;
#pragma unroll
        for (int ks = 0; ks < 4; ks++) {
            const uint32_t cz = (uint32_t)(((2*ks + hi) ^ rsw) << 4);
            uint32_t a[2][4];
            ldsm4(a[0][0], a[0][1], a[0][2], a[0][3], sb + aRow[0] + cz);
            ldsm4(a[1][0], a[1][1], a[1][2], a[1][3], sb + aRow[1] + cz);
            uint32_t b[8][2];
#pragma unroll
            for (int bt = 0; bt < 4; bt++) {
                uint32_t r0, r1, r2, r3;
                ldsm4(r0, r1, r2, r3, sb + bRow[bt] + cz);
                b[2*bt+0][0] = r0; b[2*bt+0][1] = r2;
                b[2*bt+1][0] = r1; b[2*bt+1][1] = r3;
            }
#pragma unroll
            for (int mt = 0; mt < 2; mt++)
#pragma unroll
                for (int nt = 0; nt < 8; nt++)
                    mma16816(acc[mt][nt], a[mt], b[nt]);
        }
    }

    const int er = lane >> 2;
    const int ec = (lane & 3) * 2;
#pragma unroll
    for (int mt = 0; mt < 2; mt++) {
#pragma unroll
        for (int nt = 0; nt < 8; nt++) {
            const int row = bm + wm*32 + mt*16 + er;
            const int col = bn + wn*64 + nt*8 + ec;
            float v00 = acc[mt][nt][0]*mul, v01 = acc[mt][nt][1]*mul;
            float v10 = acc[mt][nt][2]*mul, v11 = acc[mt][nt][3]*mul;
            if (!SPLIT) {
                *(float2*)&C[(size_t)row       * DIM + col] = make_float2(v00, v01);
                *(float2*)&C[(size_t)(row + 8) * DIM + col] = make_float2(v10, v11);
            } else {
                uint32_t hp, lp;
                split2(v00, v01, hp, lp);
                *(uint32_t*)&Ch[(size_t)row * DIM + col] = hp;
                *(uint32_t*)&Cl[(size_t)row * DIM + col] = lp;
                split2(v10, v11, hp, lp);
                *(uint32_t*)&Ch[(size_t)(row + 8) * DIM + col] = hp;
                *(uint32_t*)&Cl[(size_t)(row + 8) * DIM + col] = lp;
            }
        }
    }
}

// =====================================================================
// HMMA flash attention, everything hi/lo split.
// Block = 128 threads (4 warps), 64 q-rows. Grid (32 qt, 16 h, 2 b).
// smem tiles [64 rows][256B], 16-chunk xor swizzle.
// S = Qh.Kh + Qh.Kl + Ql.Kh   (Q pre-scaled by 1/sqrt(d))
// O = Ph.Vh + Ph.Vl + Pl.Vh   (P split in registers)
// =====================================================================
#define TILEB   16384
#define SQH     0
#define SQL     (1*TILEB)
#define SKH     (2*TILEB)
#define SKL     (3*TILEB)
#define SVH     (4*TILEB)
#define SVL     (5*TILEB)
#define ASMEM   (6*TILEB)     // 98304

__global__ __launch_bounds__(128, 2)
void attn_mma(const __nv_bfloat16* __restrict__ Qh, const __nv_bfloat16* __restrict__ Ql,
              const __nv_bfloat16* __restrict__ Kh, const __nv_bfloat16* __restrict__ Kl,
              const __nv_bfloat16* __restrict__ Vh, const __nv_bfloat16* __restrict__ Vl,
              __nv_bfloat16* __restrict__ AOh, __nv_bfloat16* __restrict__ AOl)
{
    extern __shared__ __align__(128) char asm_[];
    const uint32_t smb = smem_u32(asm_);

    const int tid  = threadIdx.x;
    const int lane = tid & 31;
    const int w    = tid >> 5;

    const int qt = blockIdx.x;
    const int h  = blockIdx.y;
    const int b  = blockIdx.z;
    const int q0 = qt * 64;

    // loader mapping: thread -> (row = tid>>1, chunks half*8+c)
    const int lrow  = tid >> 1;
    const int lhalf = tid & 1;
    const size_t gq0 = (size_t)(b*SEQ + q0 + lrow) * DIM + h*HDIM + lhalf*64;
    uint32_t sdst[8];
#pragma unroll
    for (int c = 0; c < 8; c++)
        sdst[c] = smb + (uint32_t)lrow*256 + (uint32_t)(((lhalf*8 + c) ^ (lrow & 7)) << 4);

    // Q tiles (once)
#pragma unroll
    for (int c = 0; c < 8; c++) {
        cp_async16(sdst[c] + SQH, Qh + gq0 + c*8);
        cp_async16(sdst[c] + SQL, Ql + gq0 + c*8);
    }
    cp_commit();

    // mma addressing
    const int lr  = lane & 15;
    const int hi4 = lane >> 4;
    const int rsw = lr & 7;
    const uint32_t aRow = smb + (uint32_t)(w*16 + lr) * 256;
    uint32_t bRow[4];
#pragma unroll
    for (int bt = 0; bt < 4; bt++) bRow[bt] = smb + (uint32_t)(bt*16 + lr) * 256;

    const int r  = lane >> 2;
    const int q2 = (lane & 3) * 2;

    float acc_o[16][4];
#pragma unroll
    for (int nt = 0; nt < 16; nt++)
#pragma unroll
        for (int e = 0; e < 4; e++) acc_o[nt][e] = 0.f;
    float m0 = -1e30f, m1 = -1e30f, l0 = 0.f, l1 = 0.f;

    const int nkv = min(32, qt + 3);

    for (int kb = 0; kb < nkv; kb++) {
        const int kv0 = kb * 64;
        __syncthreads();   // previous compute done reading K/V smem

        // issue K then V loads
        const size_t gk0 = (size_t)(b*SEQ + kv0 + lrow) * DIM + h*HDIM + lhalf*64;
#pragma unroll
        for (int c = 0; c < 8; c++) {
            cp_async16(sdst[c] + SKH, Kh + gk0 + c*8);
            cp_async16(sdst[c] + SKL, Kl + gk0 + c*8);
        }
        cp_commit();
#pragma unroll
        for (int c = 0; c < 8; c++) {
            cp_async16(sdst[c] + SVH, Vh + gk0 + c*8);
            cp_async16(sdst[c] + SVL, Vl + gk0 + c*8);
        }
        cp_commit();
        cp_wait<1>();      // K (and Q on first iter) ready
        __syncthreads();

        // ---- S = Q.K^T : 3 passes over hi/lo ----
        float s[8][4];
#pragma unroll
        for (int nt = 0; nt < 8; nt++)
#pragma unroll
            for (int e = 0; e < 4; e++) s[nt][e] = 0.f;

#pragma unroll
        for (int pass = 0; pass < 3; pass++) {
            const uint32_t aB = aRow + ((pass < 2) ? SQH : SQL);
            const uint32_t bB = (pass == 1) ? SKL : SKH;
#pragma unroll
            for (int ks = 0; ks < 8; ks++) {
                const uint32_t cz = (uint32_t)(((2*ks + hi4) ^ rsw) << 4);
                uint32_t a[4];
                ldsm4(a[0], a[1], a[2], a[3], aB + cz);
                uint32_t bb[8][2];
#pragma unroll
                for (int bt = 0; bt < 4; bt++) {
                    uint32_t r0, r1, r2, r3;
                    ldsm4(r0, r1, r2, r3, bRow[bt] + bB + cz);
                    bb[2*bt+0][0] = r0; bb[2*bt+0][1] = r2;
                    bb[2*bt+1][0] = r1; bb[2*bt+1][1] = r3;
                }
#pragma unroll
                for (int nt = 0; nt < 8; nt++)
                    mma16816(s[nt], a, bb[nt]);
            }
        }

        // ---- mask (only tile kb == qt+2 crosses the boundary) ----
        if (kb == qt + 2) {
            const int i0 = q0 + w*16 + r;
#pragma unroll
            for (int nt = 0; nt < 8; nt++) {
                const int j = kv0 + nt*8 + q2;
                if (j     - i0 > WINHALF)       s[nt][0] = -1e30f;
                if (j + 1 - i0 > WINHALF)       s[nt][1] = -1e30f;
                if (j     - (i0+8) > WINHALF)   s[nt][2] = -1e30f;
                if (j + 1 - (i0+8) > WINHALF)   s[nt][3] = -1e30f;
            }
        }

        // ---- online softmax ----
        float mx0 = -1e30f, mx1 = -1e30f;
#pragma unroll
        for (int nt = 0; nt < 8; nt++) {
            mx0 = fmaxf(mx0, fmaxf(s[nt][0], s[nt][1]));
            mx1 = fmaxf(mx1, fmaxf(s[nt][2], s[nt][3]));
        }
        mx0 = fmaxf(mx0, __shfl_xor_sync(0xffffffffu, mx0, 1));
        mx0 = fmaxf(mx0, __shfl_xor_sync(0xffffffffu, mx0, 2));
        mx1 = fmaxf(mx1, __shfl_xor_sync(0xffffffffu, mx1, 1));
        mx1 = fmaxf(mx1, __shfl_xor_sync(0xffffffffu, mx1, 2));

        const float mn0 = fmaxf(m0, mx0);
        const float mn1 = fmaxf(m1, mx1);
        const float al0 = __expf(m0 - mn0);
        const float al1 = __expf(m1 - mn1);
        m0 = mn0; m1 = mn1;

        float rs0 = 0.f, rs1 = 0.f;
#pragma unroll
        for (int nt = 0; nt < 8; nt++) {
            s[nt][0] = __expf(s[nt][0] - mn0);
            s[nt][1] = __expf(s[nt][1] - mn0);
            s[nt][2] = __expf(s[nt][2] - mn1);
            s[nt][3] = __expf(s[nt][3] - mn1);
            rs0 += s[nt][0] + s[nt][1];
            rs1 += s[nt][2] + s[nt][3];
        }
        rs0 += __shfl_xor_sync(0xffffffffu, rs0, 1);
        rs0 += __shfl_xor_sync(0xffffffffu, rs0, 2);
        rs1 += __shfl_xor_sync(0xffffffffu, rs1, 1);
        rs1 += __shfl_xor_sync(0xffffffffu, rs1, 2);
        l0 = l0 * al0 + rs0;
        l1 = l1 * al1 + rs1;

#pragma unroll
        for (int nt = 0; nt < 16; nt++) {
            acc_o[nt][0] *= al0; acc_o[nt][1] *= al0;
            acc_o[nt][2] *= al1; acc_o[nt][3] *= al1;
        }

        cp_wait<0>();      // V ready
        __syncthreads();

        // ---- O += P.V : P split, V hi/lo via ldmatrix.trans ----
#pragma unroll
        for (int kt = 0; kt < 4; kt++) {
            uint32_t ah[4], al_[4];
            split2(s[2*kt][0],   s[2*kt][1],   ah[0], al_[0]);
            split2(s[2*kt][2],   s[2*kt][3],   ah[1], al_[1]);
            split2(s[2*kt+1][0], s[2*kt+1][1], ah[2], al_[2]);
            split2(s[2*kt+1][2], s[2*kt+1][3], ah[3], al_[3]);

            const int jrow = kt*16 + lr;
            const uint32_t vbase = smb + (uint32_t)jrow * 256;
#pragma unroll
            for (int cp = 0; cp < 8; cp++) {
                const uint32_t coff = (uint32_t)(((2*cp + hi4) ^ (jrow & 7)) << 4);
                uint32_t h0, h1, h2, h3;
                ldsm4t(h0, h1, h2, h3, vbase + SVH + coff);
                uint32_t bh0[2] = {h0, h1}, bh1[2] = {h2, h3};
                mma16816(acc_o[2*cp],   ah,  bh0);
                mma16816(acc_o[2*cp+1], ah,  bh1);
                mma16816(acc_o[2*cp],   al_, bh0);
                mma16816(acc_o[2*cp+1], al_, bh1);
                uint32_t l0r, l1r, l2r, l3r;
                ldsm4t(l0r, l1r, l2r, l3r, vbase + SVL + coff);
                uint32_t bl0[2] = {l0r, l1r}, bl1[2] = {l2r, l3r};
                mma16816(acc_o[2*cp],   ah, bl0);
                mma16816(acc_o[2*cp+1], ah, bl1);
            }
        }
    }

    // ---- epilogue: normalize, hi/lo split, store ----
    const float inv0 = 1.0f / l0;
    const float inv1 = 1.0f / l1;
    const size_t row0 = (size_t)(b*SEQ + q0 + w*16 + r) * DIM;
    const size_t row1 = row0 + 8*DIM;
#pragma unroll
    for (int nt = 0; nt < 16; nt++) {
        const int col = h*HDIM + nt*8 + q2;
        uint32_t hp, lp;
        split2(acc_o[nt][0]*inv0, acc_o[nt][1]*inv0, hp, lp);
        *(uint32_t*)&AOh[row0 + col] = hp;
        *(uint32_t*)&AOl[row0 + col] = lp;
        split2(acc_o[nt][2]*inv1, acc_o[nt][3]*inv1, hp, lp);
        *(uint32_t*)&AOh[row1 + col] = hp;
        *(uint32_t*)&AOl[row1 + col] = lp;
    }
}

// =====================================================================
// Host launch
// =====================================================================
extern "C" void kernel_launch(void* const* d_in, const int* in_sizes, int n_in,
                              void* d_out, int out_size)
{
    const float* x  = (const float*)d_in[0];
    const float* wq = (const float*)d_in[1];
    const float* wk = (const float*)d_in[2];
    const float* wv = (const float*)d_in[3];
    const float* wo = (const float*)d_in[4];
    float* out = (float*)d_out;

    __nv_bfloat16 *xh, *xl, *wh, *wl, *qh, *ql, *kh, *kl, *vh, *vl, *aoh, *aol;
    cudaGetSymbolAddress((void**)&xh,  g_xh);
    cudaGetSymbolAddress((void**)&xl,  g_xl);
    cudaGetSymbolAddress((void**)&wh,  g_wh);
    cudaGetSymbolAddress((void**)&wl,  g_wl);
    cudaGetSymbolAddress((void**)&qh,  g_qh);
    cudaGetSymbolAddress((void**)&ql,  g_ql);
    cudaGetSymbolAddress((void**)&kh,  g_kh);
    cudaGetSymbolAddress((void**)&kl,  g_kl);
    cudaGetSymbolAddress((void**)&vh,  g_vh);
    cudaGetSymbolAddress((void**)&vl,  g_vl);
    cudaGetSymbolAddress((void**)&aoh, g_aoh);
    cudaGetSymbolAddress((void**)&aol, g_aol);

    cudaFuncSetAttribute(gemm_mma<true>,  cudaFuncAttributeMaxDynamicSharedMemorySize, GSMEM);
    cudaFuncSetAttribute(gemm_mma<false>, cudaFuncAttributeMaxDynamicSharedMemorySize, GSMEM);
    cudaFuncSetAttribute(attn_mma,        cudaFuncAttributeMaxDynamicSharedMemorySize, ASMEM);

    // ---- splits ----
    split_kernel<<<(MROWS*DIM/4 + 255)/256, 256>>>(x, xh, xl, MROWS*DIM/4);
    const float* ws[4] = {wq, wk, wv, wo};
    for (int i = 0; i < 4; i++)
        split_kernel<<<(DIM*DIM/4 + 255)/256, 256>>>(ws[i],
            wh + (size_t)i * DIM * DIM, wl + (size_t)i * DIM * DIM, DIM*DIM/4);

    // ---- projections (Q pre-scaled by 1/sqrt(d)) ----
    dim3 gg(DIM/128, MROWS/128);
    gemm_mma<true><<<gg, 256, GSMEM>>>(xh, xl, wh + 0*(size_t)DIM*DIM, wl + 0*(size_t)DIM*DIM,
                                       nullptr, qh, ql, SCALE);
    gemm_mma<true><<<gg, 256, GSMEM>>>(xh, xl, wh + 1*(size_t)DIM*DIM, wl + 1*(size_t)DIM*DIM,
                                       nullptr, kh, kl, 1.0f);
    gemm_mma<true><<<gg, 256, GSMEM>>>(xh, xl, wh + 2*(size_t)DIM*DIM, wl + 2*(size_t)DIM*DIM,
                                       nullptr, vh, vl, 1.0f);

    // ---- attention ----
    dim3 att_grid(SEQ/64, NHEADS, BATCH);
    attn_mma<<<att_grid, 128, ASMEM>>>(qh, ql, kh, kl, vh, vl, aoh, aol);

    // ---- output projection ----
    gemm_mma<false><<<gg, 256, GSMEM>>>(aoh, aol, wh + 3*(size_t)DIM*DIM, wl + 3*(size_t)DIM*DIM,
                                        out, nullptr, nullptr, 1.0f);
}

// round 5
// speedup vs baseline: 2.5719x; 1.0593x over previous
#include <cuda_runtime.h>
#include <cuda_bf16.h>
#include <math.h>
#include <stdint.h>

// Problem constants
#define DIM     2048
#define NHEADS  16
#define HDIM    128
#define BATCH   2
#define SEQ     2048
#define MROWS   (BATCH*SEQ)     // 4096
#define WINHALF 128             // allowed: j - i <= 128
#define SCALE   0.08838834764831845f

// ---------------- scratch (device globals: no allocation allowed) -------------
__device__ __nv_bfloat16 g_xh [MROWS*DIM];
__device__ __nv_bfloat16 g_xl [MROWS*DIM];
__device__ __nv_bfloat16 g_wh [4*DIM*DIM];
__device__ __nv_bfloat16 g_wl [4*DIM*DIM];
__device__ __nv_bfloat16 g_qh [MROWS*DIM];
__device__ __nv_bfloat16 g_ql [MROWS*DIM];
__device__ __nv_bfloat16 g_kh [MROWS*DIM];
__device__ __nv_bfloat16 g_kl [MROWS*DIM];
__device__ __nv_bfloat16 g_vh [MROWS*DIM];
__device__ __nv_bfloat16 g_vl [MROWS*DIM];
__device__ __nv_bfloat16 g_aoh[MROWS*DIM];
__device__ __nv_bfloat16 g_aol[MROWS*DIM];

// =====================================================================
// low-level helpers (base ISA only)
// =====================================================================
__device__ __forceinline__ uint32_t smem_u32(const void* p) {
    uint32_t a;
    asm("{ .reg .u64 t; cvta.to.shared.u64 t, %1; cvt.u32.u64 %0, t; }"
        : "=r"(a) : "l"(p));
    return a;
}
__device__ __forceinline__ void cp_async16(uint32_t d, const void* g) {
    uint64_t ga = (uint64_t)__cvta_generic_to_global(g);
    asm volatile("cp.async.cg.shared.global [%0], [%1], 16;" :: "r"(d), "l"(ga));
}
__device__ __forceinline__ void cp_commit() {
    asm volatile("cp.async.commit_group;" ::: "memory");
}
template<int N> __device__ __forceinline__ void cp_wait() {
    asm volatile("cp.async.wait_group %0;" :: "n"(N) : "memory");
}
__device__ __forceinline__ void ldsm4(uint32_t& r0, uint32_t& r1,
                                      uint32_t& r2, uint32_t& r3, uint32_t a) {
    asm volatile("ldmatrix.sync.aligned.m8n8.x4.shared.b16 {%0,%1,%2,%3}, [%4];"
                 : "=r"(r0), "=r"(r1), "=r"(r2), "=r"(r3) : "r"(a));
}
__device__ __forceinline__ void ldsm4t(uint32_t& r0, uint32_t& r1,
                                       uint32_t& r2, uint32_t& r3, uint32_t a) {
    asm volatile("ldmatrix.sync.aligned.m8n8.x4.trans.shared.b16 {%0,%1,%2,%3}, [%4];"
                 : "=r"(r0), "=r"(r1), "=r"(r2), "=r"(r3) : "r"(a));
}
__device__ __forceinline__ void mma16816(float* d, const uint32_t* a, const uint32_t* b) {
    asm volatile(
        "mma.sync.aligned.m16n8k16.row.col.f32.bf16.bf16.f32 "
        "{%0,%1,%2,%3}, {%4,%5,%6,%7}, {%8,%9}, {%0,%1,%2,%3};"
        : "+f"(d[0]), "+f"(d[1]), "+f"(d[2]), "+f"(d[3])
        : "r"(a[0]), "r"(a[1]), "r"(a[2]), "r"(a[3]), "r"(b[0]), "r"(b[1]));
}
__device__ __forceinline__ void split2(float a, float b, uint32_t& hp, uint32_t& lp) {
    __nv_bfloat16 ha = __float2bfloat16(a), hb = __float2bfloat16(b);
    float ra = a - __bfloat162float(ha);
    float rb = b - __bfloat162float(hb);
    __nv_bfloat162 h = __halves2bfloat162(ha, hb);
    __nv_bfloat162 l = __halves2bfloat162(__float2bfloat16(ra), __float2bfloat16(rb));
    hp = *(uint32_t*)&h;
    lp = *(uint32_t*)&l;
}

// =====================================================================
// Split fp32 -> (hi, lo) bf16
// =====================================================================
__global__ void split_kernel(const float* __restrict__ src,
                             __nv_bfloat16* __restrict__ hi,
                             __nv_bfloat16* __restrict__ lo, int n4)
{
    int i = blockIdx.x * blockDim.x + threadIdx.x;
    if (i >= n4) return;
    float4 v = ((const float4*)src)[i];
    uint32_t h0, l0, h1, l1;
    split2(v.x, v.y, h0, l0);
    split2(v.z, v.w, h1, l1);
    ((uint2*)hi)[i] = make_uint2(h0, h1);
    ((uint2*)lo)[i] = make_uint2(l0, l1);
}

// fused 4-matrix weight split (all 4 weights in one launch)
__global__ void split4_kernel(const float* __restrict__ s0, const float* __restrict__ s1,
                              const float* __restrict__ s2, const float* __restrict__ s3,
                              __nv_bfloat16* __restrict__ hi, __nv_bfloat16* __restrict__ lo,
                              int n4each)
{
    int i = blockIdx.x * blockDim.x + threadIdx.x;
    if (i >= 4*n4each) return;
    const int wsel = i / n4each;
    const int j    = i - wsel * n4each;
    const float* src = (wsel == 0) ? s0 : (wsel == 1) ? s1 : (wsel == 2) ? s2 : s3;
    float4 v = ((const float4*)src)[j];
    uint32_t h0, l0, h1, l1;
    split2(v.x, v.y, h0, l0);
    split2(v.z, v.w, h1, l1);
    ((uint2*)hi)[i] = make_uint2(h0, h1);
    ((uint2*)lo)[i] = make_uint2(l0, l1);
}

// =====================================================================
// HMMA GEMM:  C = mul * (Ah*Bh^T + Ah*Bl^T + Al*Bh^T)
// Combined-pass: all 4 tiles (Ah,Al,Bh,Bl) per k-chunk in one stage.
// CTA tile 128x128, BK=64, 3-stage pipeline (192KB smem), 8 warps.
// =====================================================================
#define GBM     128
#define GBN     128
#define GBK     64
#define GSTAGES 3
#define GTILE   16384               // 128 rows x 128 bytes
#define TAH     0
#define TAL     (1*GTILE)
#define TBH     (2*GTILE)
#define TBL     (3*GTILE)
#define GSTG    (4*GTILE)           // 64KB per stage
#define GSMEM   (GSTAGES*GSTG)      // 196608
#define GNIT    32                  // k-chunks

template<bool SPLIT>
__global__ __launch_bounds__(256, 1)
void gemm_mma(const __nv_bfloat16* __restrict__ Ah, const __nv_bfloat16* __restrict__ Al,
              const __nv_bfloat16* __restrict__ Bh, const __nv_bfloat16* __restrict__ Bl,
              float* __restrict__ C,
              __nv_bfloat16* __restrict__ Ch, __nv_bfloat16* __restrict__ Cl,
              float mul)
{
    extern __shared__ __align__(128) char gsm[];
    const uint32_t smb = smem_u32(gsm);

    const int tid  = threadIdx.x;
    const int lane = tid & 31;
    const int warp = tid >> 5;
    const int wm   = warp >> 1;
    const int wn   = warp & 1;
    const int bm   = blockIdx.y * GBM;
    const int bn   = blockIdx.x * GBN;

    const int lr  = lane & 15;
    const int hi  = lane >> 4;
    const int rsw = lr & 7;
    uint32_t aRow[2], bRow[4];
#pragma unroll
    for (int mt = 0; mt < 2; mt++) aRow[mt] = (uint32_t)(wm*32 + mt*16 + lr) * 128;
#pragma unroll
    for (int bt = 0; bt < 4; bt++) bRow[bt] = (uint32_t)(wn*64 + bt*16 + lr) * 128;

    int ldr[4], ldc[4];
#pragma unroll
    for (int i = 0; i < 4; i++) {
        int id = tid + 256*i;
        ldr[i] = id >> 3;
        ldc[i] = id & 7;
    }

    float acc[2][8][4];
#pragma unroll
    for (int mt = 0; mt < 2; mt++)
#pragma unroll
        for (int nt = 0; nt < 8; nt++)
#pragma unroll
            for (int e = 0; e < 4; e++) acc[mt][nt][e] = 0.f;

    auto load_stage = [&](int it) {
        if (it >= GNIT) return;
        const int k0 = it * GBK;
        const uint32_t sb = smb + (uint32_t)(it % GSTAGES) * GSTG;
#pragma unroll
        for (int i = 0; i < 4; i++) {
            const int r = ldr[i], c = ldc[i];
            const uint32_t dof = (uint32_t)r * 128 + (uint32_t)((c ^ (r & 7)) << 4);
            const size_t ga = (size_t)(bm + r) * DIM + k0 + c*8;
            const size_t gb = (size_t)(bn + r) * DIM + k0 + c*8;
            cp_async16(sb + TAH + dof, Ah + ga);
            cp_async16(sb + TAL + dof, Al + ga);
            cp_async16(sb + TBH + dof, Bh + gb);
            cp_async16(sb + TBL + dof, Bl + gb);
        }
    };

    load_stage(0); cp_commit();
    load_stage(1); cp_commit();

    for (int it = 0; it < GNIT; it++) {
        cp_wait<1>();
        __syncthreads();

        load_stage(it + 2); cp_commit();

        const uint32_t sb = smb + (uint32_t)(it % GSTAGES) * GSTG;
#pragma unroll
        for (int ks = 0; ks < 4; ks++) {
            const uint32_t cz = (uint32_t)(((2*ks + hi) ^ rsw) << 4);
            uint32_t ah[2][4], al_[2][4];
            ldsm4(ah[0][0],  ah[0][1],  ah[0][2],  ah[0][3],  sb + TAH + aRow[0] + cz);
            ldsm4(ah[1][0],  ah[1][1],  ah[1][2],  ah[1][3],  sb + TAH + aRow[1] + cz);
            ldsm4(al_[0][0], al_[0][1], al_[0][2], al_[0][3], sb + TAL + aRow[0] + cz);
            ldsm4(al_[1][0], al_[1][1], al_[1][2], al_[1][3], sb + TAL + aRow[1] + cz);
            uint32_t bh[8][2], bl[8][2];
#pragma unroll
            for (int bt = 0; bt < 4; bt++) {
                uint32_t r0, r1, r2, r3;
                ldsm4(r0, r1, r2, r3, sb + TBH + bRow[bt] + cz);
                bh[2*bt+0][0] = r0; bh[2*bt+0][1] = r2;
                bh[2*bt+1][0] = r1; bh[2*bt+1][1] = r3;
                ldsm4(r0, r1, r2, r3, sb + TBL + bRow[bt] + cz);
                bl[2*bt+0][0] = r0; bl[2*bt+0][1] = r2;
                bl[2*bt+1][0] = r1; bl[2*bt+1][1] = r3;
            }
#pragma unroll
            for (int mt = 0; mt < 2; mt++)
#pragma unroll
                for (int nt = 0; nt < 8; nt++) {
                    mma16816(acc[mt][nt], ah[mt],  bh[nt]);
                    mma16816(acc[mt][nt], ah[mt],  bl[nt]);
                    mma16816(acc[mt][nt], al_[mt], bh[nt]);
                }
        }
    }

    const int er = lane >> 2;
    const int ec = (lane & 3) * 2;
#pragma unroll
    for (int mt = 0; mt < 2; mt++) {
#pragma unroll
        for (int nt = 0; nt < 8; nt++) {
            const int row = bm + wm*32 + mt*16 + er;
            const int col = bn + wn*64 + nt*8 + ec;
            float v00 = acc[mt][nt][0]*mul, v01 = acc[mt][nt][1]*mul;
            float v10 = acc[mt][nt][2]*mul, v11 = acc[mt][nt][3]*mul;
            if (!SPLIT) {
                *(float2*)&C[(size_t)row       * DIM + col] = make_float2(v00, v01);
                *(float2*)&C[(size_t)(row + 8) * DIM + col] = make_float2(v10, v11);
            } else {
                uint32_t hp, lp;
                split2(v00, v01, hp, lp);
                *(uint32_t*)&Ch[(size_t)row * DIM + col] = hp;
                *(uint32_t*)&Cl[(size_t)row * DIM + col] = lp;
                split2(v10, v11, hp, lp);
                *(uint32_t*)&Ch[(size_t)(row + 8) * DIM + col] = hp;
                *(uint32_t*)&Cl[(size_t)(row + 8) * DIM + col] = lp;
            }
        }
    }
}

// =====================================================================
// HMMA flash attention, hi/lo split, combined QK passes.
// Block = 128 threads (4 warps), 64 q-rows. Grid (32 qt, 16 h, 2 b).
// =====================================================================
#define TILEB   16384
#define SQH     0
#define SQL     (1*TILEB)
#define SKH     (2*TILEB)
#define SKL     (3*TILEB)
#define SVH     (4*TILEB)
#define SVL     (5*TILEB)
#define ASMEM   (6*TILEB)     // 98304

__global__ __launch_bounds__(128, 2)
void attn_mma(const __nv_bfloat16* __restrict__ Qh, const __nv_bfloat16* __restrict__ Ql,
              const __nv_bfloat16* __restrict__ Kh, const __nv_bfloat16* __restrict__ Kl,
              const __nv_bfloat16* __restrict__ Vh, const __nv_bfloat16* __restrict__ Vl,
              __nv_bfloat16* __restrict__ AOh, __nv_bfloat16* __restrict__ AOl)
{
    extern __shared__ __align__(128) char asm_[];
    const uint32_t smb = smem_u32(asm_);

    const int tid  = threadIdx.x;
    const int lane = tid & 31;
    const int w    = tid >> 5;

    const int qt = blockIdx.x;
    const int h  = blockIdx.y;
    const int b  = blockIdx.z;
    const int q0 = qt * 64;

    const int lrow  = tid >> 1;
    const int lhalf = tid & 1;
    const size_t gq0 = (size_t)(b*SEQ + q0 + lrow) * DIM + h*HDIM + lhalf*64;
    uint32_t sdst[8];
#pragma unroll
    for (int c = 0; c < 8; c++)
        sdst[c] = smb + (uint32_t)lrow*256 + (uint32_t)(((lhalf*8 + c) ^ (lrow & 7)) << 4);

#pragma unroll
    for (int c = 0; c < 8; c++) {
        cp_async16(sdst[c] + SQH, Qh + gq0 + c*8);
        cp_async16(sdst[c] + SQL, Ql + gq0 + c*8);
    }
    cp_commit();

    const int lr  = lane & 15;
    const int hi4 = lane >> 4;
    const int rsw = lr & 7;
    const uint32_t aRow = smb + (uint32_t)(w*16 + lr) * 256;
    uint32_t bRow[4];
#pragma unroll
    for (int bt = 0; bt < 4; bt++) bRow[bt] = smb + (uint32_t)(bt*16 + lr) * 256;

    const int r  = lane >> 2;
    const int q2 = (lane & 3) * 2;

    float acc_o[16][4];
#pragma unroll
    for (int nt = 0; nt < 16; nt++)
#pragma unroll
        for (int e = 0; e < 4; e++) acc_o[nt][e] = 0.f;
    float m0 = -1e30f, m1 = -1e30f, l0 = 0.f, l1 = 0.f;

    const int nkv = min(32, qt + 3);

    for (int kb = 0; kb < nkv; kb++) {
        const int kv0 = kb * 64;
        __syncthreads();

        const size_t gk0 = (size_t)(b*SEQ + kv0 + lrow) * DIM + h*HDIM + lhalf*64;
#pragma unroll
        for (int c = 0; c < 8; c++) {
            cp_async16(sdst[c] + SKH, Kh + gk0 + c*8);
            cp_async16(sdst[c] + SKL, Kl + gk0 + c*8);
        }
        cp_commit();
#pragma unroll
        for (int c = 0; c < 8; c++) {
            cp_async16(sdst[c] + SVH, Vh + gk0 + c*8);
            cp_async16(sdst[c] + SVL, Vl + gk0 + c*8);
        }
        cp_commit();
        cp_wait<1>();
        __syncthreads();

        // ---- S = Q.K^T : combined hi/lo per k-step ----
        float s[8][4];
#pragma unroll
        for (int nt = 0; nt < 8; nt++)
#pragma unroll
            for (int e = 0; e < 4; e++) s[nt][e] = 0.f;

#pragma unroll
        for (int ks = 0; ks < 8; ks++) {
            const uint32_t cz = (uint32_t)(((2*ks + hi4) ^ rsw) << 4);
            uint32_t qh[4], ql_[4];
            ldsm4(qh[0],  qh[1],  qh[2],  qh[3],  aRow + SQH + cz);
            ldsm4(ql_[0], ql_[1], ql_[2], ql_[3], aRow + SQL + cz);
            uint32_t kh[8][2], kl[8][2];
#pragma unroll
            for (int bt = 0; bt < 4; bt++) {
                uint32_t r0, r1, r2, r3;
                ldsm4(r0, r1, r2, r3, bRow[bt] + SKH + cz);
                kh[2*bt+0][0] = r0; kh[2*bt+0][1] = r2;
                kh[2*bt+1][0] = r1; kh[2*bt+1][1] = r3;
                ldsm4(r0, r1, r2, r3, bRow[bt] + SKL + cz);
                kl[2*bt+0][0] = r0; kl[2*bt+0][1] = r2;
                kl[2*bt+1][0] = r1; kl[2*bt+1][1] = r3;
            }
#pragma unroll
            for (int nt = 0; nt < 8; nt++) {
                mma16816(s[nt], qh,  kh[nt]);
                mma16816(s[nt], qh,  kl[nt]);
                mma16816(s[nt], ql_, kh[nt]);
            }
        }

        // ---- mask (only tile kb == qt+2 crosses the boundary) ----
        if (kb == qt + 2) {
            const int i0 = q0 + w*16 + r;
#pragma unroll
            for (int nt = 0; nt < 8; nt++) {
                const int j = kv0 + nt*8 + q2;
                if (j     - i0 > WINHALF)       s[nt][0] = -1e30f;
                if (j + 1 - i0 > WINHALF)       s[nt][1] = -1e30f;
                if (j     - (i0+8) > WINHALF)   s[nt][2] = -1e30f;
                if (j + 1 - (i0+8) > WINHALF)   s[nt][3] = -1e30f;
            }
        }

        // ---- online softmax ----
        float mx0 = -1e30f, mx1 = -1e30f;
#pragma unroll
        for (int nt = 0; nt < 8; nt++) {
            mx0 = fmaxf(mx0, fmaxf(s[nt][0], s[nt][1]));
            mx1 = fmaxf(mx1, fmaxf(s[nt][2], s[nt][3]));
        }
        mx0 = fmaxf(mx0, __shfl_xor_sync(0xffffffffu, mx0, 1));
        mx0 = fmaxf(mx0, __shfl_xor_sync(0xffffffffu, mx0, 2));
        mx1 = fmaxf(mx1, __shfl_xor_sync(0xffffffffu, mx1, 1));
        mx1 = fmaxf(mx1, __shfl_xor_sync(0xffffffffu, mx1, 2));

        const float mn0 = fmaxf(m0, mx0);
        const float mn1 = fmaxf(m1, mx1);
        const float al0 = __expf(m0 - mn0);
        const float al1 = __expf(m1 - mn1);
        m0 = mn0; m1 = mn1;

        float rs0 = 0.f, rs1 = 0.f;
#pragma unroll
        for (int nt = 0; nt < 8; nt++) {
            s[nt][0] = __expf(s[nt][0] - mn0);
            s[nt][1] = __expf(s[nt][1] - mn0);
            s[nt][2] = __expf(s[nt][2] - mn1);
            s[nt][3] = __expf(s[nt][3] - mn1);
            rs0 += s[nt][0] + s[nt][1];
            rs1 += s[nt][2] + s[nt][3];
        }
        rs0 += __shfl_xor_sync(0xffffffffu, rs0, 1);
        rs0 += __shfl_xor_sync(0xffffffffu, rs0, 2);
        rs1 += __shfl_xor_sync(0xffffffffu, rs1, 1);
        rs1 += __shfl_xor_sync(0xffffffffu, rs1, 2);
        l0 = l0 * al0 + rs0;
        l1 = l1 * al1 + rs1;

#pragma unroll
        for (int nt = 0; nt < 16; nt++) {
            acc_o[nt][0] *= al0; acc_o[nt][1] *= al0;
            acc_o[nt][2] *= al1; acc_o[nt][3] *= al1;
        }

        cp_wait<0>();
        __syncthreads();

        // ---- O += P.V : P split in regs, V hi/lo via ldmatrix.trans ----
#pragma unroll
        for (int kt = 0; kt < 4; kt++) {
            uint32_t ah[4], al_[4];
            split2(s[2*kt][0],   s[2*kt][1],   ah[0], al_[0]);
            split2(s[2*kt][2],   s[2*kt][3],   ah[1], al_[1]);
            split2(s[2*kt+1][0], s[2*kt+1][1], ah[2], al_[2]);
            split2(s[2*kt+1][2], s[2*kt+1][3], ah[3], al_[3]);

            const int jrow = kt*16 + lr;
            const uint32_t vbase = smb + (uint32_t)jrow * 256;
#pragma unroll
            for (int cp = 0; cp < 8; cp++) {
                const uint32_t coff = (uint32_t)(((2*cp + hi4) ^ (jrow & 7)) << 4);
                uint32_t h0, h1, h2, h3;
                ldsm4t(h0, h1, h2, h3, vbase + SVH + coff);
                uint32_t bh0[2] = {h0, h1}, bh1[2] = {h2, h3};
                mma16816(acc_o[2*cp],   ah,  bh0);
                mma16816(acc_o[2*cp+1], ah,  bh1);
                mma16816(acc_o[2*cp],   al_, bh0);
                mma16816(acc_o[2*cp+1], al_, bh1);
                uint32_t l0r, l1r, l2r, l3r;
                ldsm4t(l0r, l1r, l2r, l3r, vbase + SVL + coff);
                uint32_t bl0[2] = {l0r, l1r}, bl1[2] = {l2r, l3r};
                mma16816(acc_o[2*cp],   ah, bl0);
                mma16816(acc_o[2*cp+1], ah, bl1);
            }
        }
    }

    // ---- epilogue: normalize, hi/lo split, store ----
    const float inv0 = 1.0f / l0;
    const float inv1 = 1.0f / l1;
    const size_t row0 = (size_t)(b*SEQ + q0 + w*16 + r) * DIM;
    const size_t row1 = row0 + 8*DIM;
#pragma unroll
    for (int nt = 0; nt < 16; nt++) {
        const int col = h*HDIM + nt*8 + q2;
        uint32_t hp, lp;
        split2(acc_o[nt][0]*inv0, acc_o[nt][1]*inv0, hp, lp);
        *(uint32_t*)&AOh[row0 + col] = hp;
        *(uint32_t*)&AOl[row0 + col] = lp;
        split2(acc_o[nt][2]*inv1, acc_o[nt][3]*inv1, hp, lp);
        *(uint32_t*)&AOh[row1 + col] = hp;
        *(uint32_t*)&AOl[row1 + col] = lp;
    }
}

// =====================================================================
// Host launch
// =====================================================================
extern "C" void kernel_launch(void* const* d_in, const int* in_sizes, int n_in,
                              void* d_out, int out_size)
{
    const float* x  = (const float*)d_in[0];
    const float* wq = (const float*)d_in[1];
    const float* wk = (const float*)d_in[2];
    const float* wv = (const float*)d_in[3];
    const float* wo = (const float*)d_in[4];
    float* out = (float*)d_out;

    __nv_bfloat16 *xh, *xl, *wh, *wl, *qh, *ql, *kh, *kl, *vh, *vl, *aoh, *aol;
    cudaGetSymbolAddress((void**)&xh,  g_xh);
    cudaGetSymbolAddress((void**)&xl,  g_xl);
    cudaGetSymbolAddress((void**)&wh,  g_wh);
    cudaGetSymbolAddress((void**)&wl,  g_wl);
    cudaGetSymbolAddress((void**)&qh,  g_qh);
    cudaGetSymbolAddress((void**)&ql,  g_ql);
    cudaGetSymbolAddress((void**)&kh,  g_kh);
    cudaGetSymbolAddress((void**)&kl,  g_kl);
    cudaGetSymbolAddress((void**)&vh,  g_vh);
    cudaGetSymbolAddress((void**)&vl,  g_vl);
    cudaGetSymbolAddress((void**)&aoh, g_aoh);
    cudaGetSymbolAddress((void**)&aol, g_aol);

    cudaFuncSetAttribute(gemm_mma<true>,  cudaFuncAttributeMaxDynamicSharedMemorySize, GSMEM);
    cudaFuncSetAttribute(gemm_mma<false>, cudaFuncAttributeMaxDynamicSharedMemorySize, GSMEM);
    cudaFuncSetAttribute(attn_mma,        cudaFuncAttributeMaxDynamicSharedMemorySize, ASMEM);

    // ---- splits ----
    split_kernel<<<(MROWS*DIM/4 + 255)/256, 256>>>(x, xh, xl, MROWS*DIM/4);
    split4_kernel<<<(4*(DIM*DIM/4) + 255)/256, 256>>>(wq, wk, wv, wo, wh, wl, DIM*DIM/4);

    // ---- projections (Q pre-scaled by 1/sqrt(d)) ----
    dim3 gg(DIM/128, MROWS/128);
    gemm_mma<true><<<gg, 256, GSMEM>>>(xh, xl, wh + 0*(size_t)DIM*DIM, wl + 0*(size_t)DIM*DIM,
                                       nullptr, qh, ql, SCALE);
    gemm_mma<true><<<gg, 256, GSMEM>>>(xh, xl, wh + 1*(size_t)DIM*DIM, wl + 1*(size_t)DIM*DIM,
                                       nullptr, kh, kl, 1.0f);
    gemm_mma<true><<<gg, 256, GSMEM>>>(xh, xl, wh + 2*(size_t)DIM*DIM, wl + 2*(size_t)DIM*DIM,
                                       nullptr, vh, vl, 1.0f);

    // ---- attention ----
    dim3 att_grid(SEQ/64, NHEADS, BATCH);
    attn_mma<<<att_grid, 128, ASMEM>>>(qh, ql, kh, kl, vh, vl, aoh, aol);

    // ---- output projection ----
    gemm_mma<false><<<gg, 256, GSMEM>>>(aoh, aol, wh + 3*(size_t)DIM*DIM, wl + 3*(size_t)DIM*DIM,
                                        out, nullptr, nullptr, 1.0f);
}